// round 9
// baseline (speedup 1.0000x reference)
#include <cuda_runtime.h>
#include <cuda_fp16.h>
#include <math.h>
#include <stdint.h>

#define NNODES 100000
#define NEDGES 640000
#define DD 128
#define SCAN_BLK 98            // ceil(100000/1024)

// Scratch (__device__ globals: allocation-free rule)
__device__ __half g_conv_h[NNODES * DD];   // conv = nodes@W2 + b2 (UNSCALED), fp16
__device__ __half g_aggv[NNODES * DD];     // agg*rsqrt(rdeg) + gvec, fp16
__device__ int    g_sdeg[NNODES];
__device__ int    g_rdeg[NNODES];
__device__ int    g_scan[NNODES];
__device__ int    g_bsum[SCAN_BLK];
__device__ int    g_boff[SCAN_BLK];
__device__ int    g_offs[NNODES];          // CSR row starts (in-edges per receiver)
__device__ int    g_cur[NNODES];
__device__ int    g_csr[NEDGES];           // sender ids grouped by receiver
__device__ float  g_rss[NNODES];           // rsqrt(max(sdeg,1))
__device__ float  g_gvec[DD];
__device__ float  g_an[DD];

// packed fp32x2 FMA
#define FMA_F32X2(acc, a, b) \
    asm("fma.rn.f32x2 %0, %1, %2, %0;" : "+l"(acc) : "l"(a), "l"(b))

__device__ __forceinline__ unsigned long long dup2(float f) {
    unsigned u = __float_as_uint(f);
    return (unsigned long long)u | ((unsigned long long)u << 32);
}
__device__ __forceinline__ float2 unpk(unsigned long long v) {
    return make_float2(__uint_as_float((unsigned)v), __uint_as_float((unsigned)(v >> 32)));
}

// ---------------------------------------------------------------- zero + gvec fused
__global__ void k_zero(const float* __restrict__ gl, const float* __restrict__ W3,
                       const float* __restrict__ b3) {
    int i = blockIdx.x * blockDim.x + threadIdx.x;
    if (i < NNODES) { g_sdeg[i] = 0; g_rdeg[i] = 0; }
    if (i < DD) g_an[i] = 0.f;
    if (blockIdx.x < DD) {
        __shared__ float red[DD];
        int c = blockIdx.x, t = threadIdx.x;
        if (t < DD) red[t] = gl[t] * W3[t * DD + c];
        __syncthreads();
        if (t < 64) red[t] += red[t + 64];
        __syncthreads();
        if (t < 32) {
            float v = red[t] + red[t + 32];
            #pragma unroll
            for (int o = 16; o > 0; o >>= 1) v += __shfl_down_sync(0xffffffff, v, o);
            if (t == 0) g_gvec[c] = v + b3[c];
        }
    }
}

// ---------------------------------------------------------------- degrees
__global__ void k_deg(const int* __restrict__ snd, const int* __restrict__ rcv) {
    int e = blockIdx.x * blockDim.x + threadIdx.x;
    if (e < NEDGES) {
        atomicAdd(&g_sdeg[snd[e]], 1);
        atomicAdd(&g_rdeg[rcv[e]], 1);
    }
}

// ---------------------------------------------------------------- prefix scan
__global__ __launch_bounds__(1024) void k_scanA() {
    __shared__ int sh[1024];
    int i = blockIdx.x * 1024 + threadIdx.x;
    int v = (i < NNODES) ? g_rdeg[i] : 0;
    sh[threadIdx.x] = v;
    __syncthreads();
    #pragma unroll
    for (int o = 1; o < 1024; o <<= 1) {
        int t = (threadIdx.x >= o) ? sh[threadIdx.x - o] : 0;
        __syncthreads();
        sh[threadIdx.x] += t;
        __syncthreads();
    }
    if (i < NNODES) g_scan[i] = sh[threadIdx.x];
    if (threadIdx.x == 1023) g_bsum[blockIdx.x] = sh[1023];
}
__global__ void k_scanB() {
    __shared__ int sh[128];
    int t = threadIdx.x;
    int v = (t < SCAN_BLK) ? g_bsum[t] : 0;
    sh[t] = v;
    __syncthreads();
    #pragma unroll
    for (int o = 1; o < 128; o <<= 1) {
        int u = (t >= o) ? sh[t - o] : 0;
        __syncthreads();
        sh[t] += u;
        __syncthreads();
    }
    if (t < SCAN_BLK) g_boff[t] = sh[t] - v;
}
__global__ void k_scanC() {
    int i = blockIdx.x * blockDim.x + threadIdx.x;
    if (i < NNODES) {
        int off = g_scan[i] - g_rdeg[i] + g_boff[i >> 10];
        g_offs[i] = off;
        g_cur[i]  = off;
        g_rss[i]  = rsqrtf(fmaxf((float)g_sdeg[i], 1.0f));
    }
}

// ---------------------------------------------------------------- CSR scatter
__global__ void k_scatter(const int* __restrict__ snd, const int* __restrict__ rcv) {
    int e = blockIdx.x * blockDim.x + threadIdx.x;
    if (e < NEDGES) {
        int r = rcv[e];
        int pos = atomicAdd(&g_cur[r], 1);
        g_csr[pos] = snd[e];
    }
}

// ---------------------------------------------------------------- f32x2 GEMM (one matrix per launch)
extern __shared__ unsigned long long As2[];   // 64KB
__global__ __launch_bounds__(256) void k_gemm(
    const float* __restrict__ A,
    const float* __restrict__ W, const float* __restrict__ bias,
    float* __restrict__ out_h, int which)
{
    const int rowBase = blockIdx.x * 64;
    const int tid = threadIdx.x;
    const int maxr = NNODES - rowBase;

    const float4* A4 = (const float4*)(A + (long)rowBase * DD);
    #pragma unroll
    for (int i = 0; i < 8; i++) {
        int idx4 = tid + i * 256;
        int row = idx4 >> 5, col4 = (idx4 & 31) << 2;
        float4 v = make_float4(0.f, 0.f, 0.f, 0.f);
        if (row < maxr) v = A4[idx4];
        unsigned long long* d = &As2[row * DD + col4];
        d[0] = dup2(v.x); d[1] = dup2(v.y); d[2] = dup2(v.z); d[3] = dup2(v.w);
    }
    __syncthreads();

    const int lane = tid & 31;
    const int ty   = tid >> 5;
    unsigned long long acc[8][2];
    #pragma unroll
    for (int i = 0; i < 8; i++) { acc[i][0] = 0ull; acc[i][1] = 0ull; }

    const unsigned long long* Asrow = &As2[ty * 8 * DD];
    #pragma unroll 8
    for (int k = 0; k < DD; k++) {
        ulonglong2 wp = *(const ulonglong2*)(W + (long)k * DD + lane * 4);
        #pragma unroll
        for (int i = 0; i < 8; i++) {
            unsigned long long ap = Asrow[i * DD + k];
            FMA_F32X2(acc[i][0], ap, wp.x);
            FMA_F32X2(acc[i][1], ap, wp.y);
        }
    }

    float4 bv = ((const float4*)bias)[lane];
    #pragma unroll
    for (int i = 0; i < 8; i++) {
        int r = ty * 8 + i;
        if (r < maxr) {
            int gr = rowBase + r;
            float2 p0 = unpk(acc[i][0]);
            float2 p1 = unpk(acc[i][1]);
            float4 o = make_float4(p0.x + bv.x, p0.y + bv.y, p1.x + bv.z, p1.y + bv.w);
            if (which) {
                __half2 h01 = __floats2half2_rn(o.x, o.y);     // UNSCALED conv
                __half2 h23 = __floats2half2_rn(o.z, o.w);
                uint2 pk;
                pk.x = *(unsigned*)&h01; pk.y = *(unsigned*)&h23;
                *(uint2*)&g_conv_h[(long)gr * DD + lane * 4] = pk;
            } else {
                ((float4*)out_h)[(long)gr * 32 + lane] = o;
            }
        }
    }
}

// ---------------------------------------------------------------- CSR pull -> aggv (fp16)
// One warp per receiver; aggv = (sum rss[s]*conv[s]) * rsqrt(rdeg) + gvec.
// Independent of h1 -> runs concurrently with the h1 GEMM.
__global__ __launch_bounds__(256) void k_gather() {
    const int tid  = threadIdx.x;
    const int lane = tid & 31;
    const int wy   = tid >> 5;
    const int r    = blockIdx.x * 8 + wy;
    if (r >= NNODES) return;

    const int start = g_offs[r];
    const int deg   = g_rdeg[r];
    float4 acc = make_float4(0.f, 0.f, 0.f, 0.f);
    int j = 0;
    for (; j + 1 < deg; j += 2) {
        int s0 = g_csr[start + j];
        int s1 = g_csr[start + j + 1];
        float w0 = g_rss[s0];
        float w1 = g_rss[s1];
        uint2 a0 = *(const uint2*)&g_conv_h[(long)s0 * DD + lane * 4];
        uint2 a1 = *(const uint2*)&g_conv_h[(long)s1 * DD + lane * 4];
        float2 p00 = __half22float2(*(__half2*)&a0.x);
        float2 p01 = __half22float2(*(__half2*)&a0.y);
        float2 p10 = __half22float2(*(__half2*)&a1.x);
        float2 p11 = __half22float2(*(__half2*)&a1.y);
        acc.x = fmaf(p00.x, w0, fmaf(p10.x, w1, acc.x));
        acc.y = fmaf(p00.y, w0, fmaf(p10.y, w1, acc.y));
        acc.z = fmaf(p01.x, w0, fmaf(p11.x, w1, acc.z));
        acc.w = fmaf(p01.y, w0, fmaf(p11.y, w1, acc.w));
    }
    if (j < deg) {
        int s0 = g_csr[start + j];
        float w0 = g_rss[s0];
        uint2 a0 = *(const uint2*)&g_conv_h[(long)s0 * DD + lane * 4];
        float2 p00 = __half22float2(*(__half2*)&a0.x);
        float2 p01 = __half22float2(*(__half2*)&a0.y);
        acc.x = fmaf(p00.x, w0, acc.x);
        acc.y = fmaf(p00.y, w0, acc.y);
        acc.z = fmaf(p01.x, w0, acc.z);
        acc.w = fmaf(p01.y, w0, acc.w);
    }
    float rs = rsqrtf(fmaxf((float)deg, 1.0f));
    float4 gv = ((const float4*)g_gvec)[lane];
    __half2 o01 = __floats2half2_rn(fmaf(acc.x, rs, gv.x), fmaf(acc.y, rs, gv.y));
    __half2 o23 = __floats2half2_rn(fmaf(acc.z, rs, gv.z), fmaf(acc.w, rs, gv.w));
    uint2 pk;
    pk.x = *(unsigned*)&o01; pk.y = *(unsigned*)&o23;
    *(uint2*)&g_aggv[(long)r * DD + lane * 4] = pk;
}

// ---------------------------------------------------------------- combine: o = relu(h1+aggv)+nodes, colsum
__global__ __launch_bounds__(256) void k_combine(const float* __restrict__ nodes,
                                                 float* __restrict__ out) {
    __shared__ float4 sred[256];
    const int tid  = threadIdx.x;
    const int lane = tid & 31;
    const int ty   = tid >> 5;
    const int rowBase = blockIdx.x * 64;
    float4 sum = make_float4(0.f, 0.f, 0.f, 0.f);

    #pragma unroll
    for (int i = 0; i < 8; i++) {
        int r = rowBase + ty * 8 + i;
        if (r < NNODES) {
            long off = (long)r * 32 + lane;
            float4 h  = ((float4*)out)[off];
            uint2 av  = *(const uint2*)&g_aggv[(long)r * DD + lane * 4];
            float2 a01 = __half22float2(*(__half2*)&av.x);
            float2 a23 = __half22float2(*(__half2*)&av.y);
            float4 nd = ((const float4*)nodes)[off];
            float4 o;
            o.x = fmaxf(h.x + a01.x, 0.f) + nd.x;
            o.y = fmaxf(h.y + a01.y, 0.f) + nd.y;
            o.z = fmaxf(h.z + a23.x, 0.f) + nd.z;
            o.w = fmaxf(h.w + a23.y, 0.f) + nd.w;
            ((float4*)out)[off] = o;
            sum.x += o.x; sum.y += o.y; sum.z += o.z; sum.w += o.w;
        }
    }
    sred[tid] = sum;
    __syncthreads();
    if (ty == 0) {
        float4 s = sred[lane];
        #pragma unroll
        for (int jj = 1; jj < 8; jj++) {
            float4 t = sred[jj * 32 + lane];
            s.x += t.x; s.y += t.y; s.z += t.z; s.w += t.w;
        }
        float* addr = &g_an[lane * 4];
        asm volatile("red.global.add.v4.f32 [%0], {%1,%2,%3,%4};"
                     :: "l"(addr), "f"(s.x), "f"(s.y), "f"(s.z), "f"(s.w)
                     : "memory");
    }
}

// ---------------------------------------------------------------- global update
__global__ void k_global(const float* __restrict__ gl, const float* __restrict__ Wg,
                         const float* __restrict__ bg, float* __restrict__ outg) {
    __shared__ float red[2 * DD];
    int c = blockIdx.x, t = threadIdx.x;
    float x = (t < DD) ? g_an[t] : gl[t - DD];
    red[t] = x * Wg[t * DD + c];
    __syncthreads();
    if (t < 128) red[t] += red[t + 128];
    __syncthreads();
    if (t < 64) red[t] += red[t + 64];
    __syncthreads();
    if (t < 32) {
        float v = red[t] + red[t + 32];
        #pragma unroll
        for (int o = 16; o > 0; o >>= 1) v += __shfl_down_sync(0xffffffff, v, o);
        if (t == 0) outg[c] = gl[c] + fmaxf(v + bg[c], 0.f);
    }
}

// ---------------------------------------------------------------- launch (forked graph)
extern "C" void kernel_launch(void* const* d_in, const int* in_sizes, int n_in,
                              void* d_out, int out_size) {
    const float* nodes    = (const float*)d_in[0];
    const float* globals_ = (const float*)d_in[1];
    const int*   senders   = (const int*)d_in[2];
    const int*   receivers = (const int*)d_in[3];
    const float* W1w = (const float*)d_in[4];
    const float* W1b = (const float*)d_in[5];
    const float* W2w = (const float*)d_in[6];
    const float* W2b = (const float*)d_in[7];
    const float* W3w = (const float*)d_in[8];
    const float* W3b = (const float*)d_in[9];
    const float* Wgw = (const float*)d_in[10];
    const float* Wgb = (const float*)d_in[11];
    float* out = (float*)d_out;

    static cudaStream_t s1 = nullptr;
    static cudaEvent_t evRoot = nullptr, evConv = nullptr, evGather = nullptr;
    if (s1 == nullptr) {
        cudaFuncSetAttribute(k_gemm, cudaFuncAttributeMaxDynamicSharedMemorySize, 64 * DD * 8);
        cudaStreamCreateWithFlags(&s1, cudaStreamNonBlocking);
        cudaEventCreateWithFlags(&evRoot, cudaEventDisableTiming);
        cudaEventCreateWithFlags(&evConv, cudaEventDisableTiming);
        cudaEventCreateWithFlags(&evGather, cudaEventDisableTiming);
    }

    const int gemm_smem = 64 * DD * 8;
    const int GEMM_BLOCKS = (NNODES + 63) / 64;

    // fork
    cudaEventRecord(evRoot, 0);
    cudaStreamWaitEvent(s1, evRoot, 0);

    // side chain (s1): zero/gvec -> degrees -> scan -> CSR scatter  (hidden under conv GEMM)
    k_zero<<<(NNODES + 255) / 256, 256, 0, s1>>>(globals_, W3w, W3b);
    k_deg<<<(NEDGES + 255) / 256, 256, 0, s1>>>(senders, receivers);
    k_scanA<<<SCAN_BLK, 1024, 0, s1>>>();
    k_scanB<<<1, 128, 0, s1>>>();
    k_scanC<<<(NNODES + 255) / 256, 256, 0, s1>>>();
    k_scatter<<<(NEDGES + 255) / 256, 256, 0, s1>>>(senders, receivers);

    // main: conv GEMM first
    k_gemm<<<GEMM_BLOCKS, 256, gemm_smem>>>(nodes, W2w, W2b, out, 1);
    cudaEventRecord(evConv, 0);

    // s1: gather (needs CSR chain [same stream] + conv [event]) — overlaps h1 GEMM
    cudaStreamWaitEvent(s1, evConv, 0);
    k_gather<<<(NNODES + 7) / 8, 256, 0, s1>>>();
    cudaEventRecord(evGather, s1);

    // main: h1 GEMM concurrently with gather
    k_gemm<<<GEMM_BLOCKS, 256, gemm_smem>>>(nodes, W1w, W1b, out, 0);

    // join -> combine -> global
    cudaStreamWaitEvent(0, evGather, 0);
    k_combine<<<GEMM_BLOCKS, 256>>>(nodes, out);
    k_global<<<DD, 2 * DD>>>(globals_, Wgw, Wgb, out + (long)NNODES * DD);
}

// round 10
// speedup vs baseline: 1.2402x; 1.2402x over previous
#include <cuda_runtime.h>
#include <cuda_fp16.h>
#include <math.h>
#include <stdint.h>

#define NNODES 100000
#define NEDGES 640000
#define DD 128
#define SCAN_BLK 98            // ceil(100000/1024)

// Scratch (__device__ globals: allocation-free rule)
__device__ __half g_conv_h[NNODES * DD];   // conv = nodes@W2 + b2 (UNSCALED), fp16
__device__ int    g_sdeg[NNODES];
__device__ int    g_rdeg[NNODES];
__device__ int    g_scan[NNODES];
__device__ int    g_bsum[SCAN_BLK];
__device__ int    g_boff[SCAN_BLK];
__device__ int    g_offs[NNODES];          // CSR row starts (in-edges per receiver)
__device__ int    g_cur[NNODES];
__device__ int    g_csr[NEDGES];           // sender ids grouped by receiver
__device__ float  g_rss[NNODES];           // rsqrt(max(sdeg,1))
__device__ float  g_gvec[DD];
__device__ float  g_an[DD];

// packed fp32x2 FMA
#define FMA_F32X2(acc, a, b) \
    asm("fma.rn.f32x2 %0, %1, %2, %0;" : "+l"(acc) : "l"(a), "l"(b))

__device__ __forceinline__ unsigned long long dup2(float f) {
    unsigned u = __float_as_uint(f);
    return (unsigned long long)u | ((unsigned long long)u << 32);
}
__device__ __forceinline__ float2 unpk(unsigned long long v) {
    return make_float2(__uint_as_float((unsigned)v), __uint_as_float((unsigned)(v >> 32)));
}

// ---------------------------------------------------------------- zero + gvec fused
__global__ void k_zero(const float* __restrict__ gl, const float* __restrict__ W3,
                       const float* __restrict__ b3) {
    int i = blockIdx.x * blockDim.x + threadIdx.x;
    if (i < NNODES) { g_sdeg[i] = 0; g_rdeg[i] = 0; }
    if (i < DD) g_an[i] = 0.f;
    if (blockIdx.x < DD) {
        __shared__ float red[DD];
        int c = blockIdx.x, t = threadIdx.x;
        if (t < DD) red[t] = gl[t] * W3[t * DD + c];
        __syncthreads();
        if (t < 64) red[t] += red[t + 64];
        __syncthreads();
        if (t < 32) {
            float v = red[t] + red[t + 32];
            #pragma unroll
            for (int o = 16; o > 0; o >>= 1) v += __shfl_down_sync(0xffffffff, v, o);
            if (t == 0) g_gvec[c] = v + b3[c];
        }
    }
}

// ---------------------------------------------------------------- degrees
__global__ void k_deg(const int* __restrict__ snd, const int* __restrict__ rcv) {
    int e = blockIdx.x * blockDim.x + threadIdx.x;
    if (e < NEDGES) {
        atomicAdd(&g_sdeg[snd[e]], 1);
        atomicAdd(&g_rdeg[rcv[e]], 1);
    }
}

// ---------------------------------------------------------------- prefix scan
__global__ __launch_bounds__(1024) void k_scanA() {
    __shared__ int sh[1024];
    int i = blockIdx.x * 1024 + threadIdx.x;
    int v = (i < NNODES) ? g_rdeg[i] : 0;
    sh[threadIdx.x] = v;
    __syncthreads();
    #pragma unroll
    for (int o = 1; o < 1024; o <<= 1) {
        int t = (threadIdx.x >= o) ? sh[threadIdx.x - o] : 0;
        __syncthreads();
        sh[threadIdx.x] += t;
        __syncthreads();
    }
    if (i < NNODES) g_scan[i] = sh[threadIdx.x];
    if (threadIdx.x == 1023) g_bsum[blockIdx.x] = sh[1023];
}
__global__ void k_scanB() {
    __shared__ int sh[128];
    int t = threadIdx.x;
    int v = (t < SCAN_BLK) ? g_bsum[t] : 0;
    sh[t] = v;
    __syncthreads();
    #pragma unroll
    for (int o = 1; o < 128; o <<= 1) {
        int u = (t >= o) ? sh[t - o] : 0;
        __syncthreads();
        sh[t] += u;
        __syncthreads();
    }
    if (t < SCAN_BLK) g_boff[t] = sh[t] - v;
}
__global__ void k_scanC() {
    int i = blockIdx.x * blockDim.x + threadIdx.x;
    if (i < NNODES) {
        int off = g_scan[i] - g_rdeg[i] + g_boff[i >> 10];
        g_offs[i] = off;
        g_cur[i]  = off;
        g_rss[i]  = rsqrtf(fmaxf((float)g_sdeg[i], 1.0f));
    }
}

// ---------------------------------------------------------------- CSR scatter
__global__ void k_scatter(const int* __restrict__ snd, const int* __restrict__ rcv) {
    int e = blockIdx.x * blockDim.x + threadIdx.x;
    if (e < NEDGES) {
        int r = rcv[e];
        int pos = atomicAdd(&g_cur[r], 1);
        g_csr[pos] = snd[e];
    }
}

// ---------------------------------------------------------------- f32x2 GEMM (both matrices, grid.y)
extern __shared__ unsigned long long As2[];   // 64KB
__global__ __launch_bounds__(256) void k_gemm(
    const float* __restrict__ A,
    const float* __restrict__ W1, const float* __restrict__ b1,
    const float* __restrict__ W2, const float* __restrict__ b2,
    float* __restrict__ out_h)
{
    const int which = blockIdx.y;
    const float* W    = which ? W2 : W1;
    const float* bias = which ? b2 : b1;
    const int rowBase = blockIdx.x * 64;
    const int tid = threadIdx.x;
    const int maxr = NNODES - rowBase;

    const float4* A4 = (const float4*)(A + (long)rowBase * DD);
    #pragma unroll
    for (int i = 0; i < 8; i++) {
        int idx4 = tid + i * 256;
        int row = idx4 >> 5, col4 = (idx4 & 31) << 2;
        float4 v = make_float4(0.f, 0.f, 0.f, 0.f);
        if (row < maxr) v = A4[idx4];
        unsigned long long* d = &As2[row * DD + col4];
        d[0] = dup2(v.x); d[1] = dup2(v.y); d[2] = dup2(v.z); d[3] = dup2(v.w);
    }
    __syncthreads();

    const int lane = tid & 31;
    const int ty   = tid >> 5;
    unsigned long long acc[8][2];
    #pragma unroll
    for (int i = 0; i < 8; i++) { acc[i][0] = 0ull; acc[i][1] = 0ull; }

    const unsigned long long* Asrow = &As2[ty * 8 * DD];
    #pragma unroll 8
    for (int k = 0; k < DD; k++) {
        ulonglong2 wp = *(const ulonglong2*)(W + (long)k * DD + lane * 4);
        #pragma unroll
        for (int i = 0; i < 8; i++) {
            unsigned long long ap = Asrow[i * DD + k];
            FMA_F32X2(acc[i][0], ap, wp.x);
            FMA_F32X2(acc[i][1], ap, wp.y);
        }
    }

    float4 bv = ((const float4*)bias)[lane];
    #pragma unroll
    for (int i = 0; i < 8; i++) {
        int r = ty * 8 + i;
        if (r < maxr) {
            int gr = rowBase + r;
            float2 p0 = unpk(acc[i][0]);
            float2 p1 = unpk(acc[i][1]);
            float4 o = make_float4(p0.x + bv.x, p0.y + bv.y, p1.x + bv.z, p1.y + bv.w);
            if (which) {
                __half2 h01 = __floats2half2_rn(o.x, o.y);     // UNSCALED conv
                __half2 h23 = __floats2half2_rn(o.z, o.w);
                uint2 pk;
                pk.x = *(unsigned*)&h01; pk.y = *(unsigned*)&h23;
                *(uint2*)&g_conv_h[(long)gr * DD + lane * 4] = pk;
            } else {
                ((float4*)out_h)[(long)gr * 32 + lane] = o;
            }
        }
    }
}

// ---------------------------------------------------------------- CSR pull + fused epilogue
__global__ __launch_bounds__(256) void k_gather(const float* __restrict__ nodes,
                                                float* __restrict__ out) {
    __shared__ float4 sred[256];
    const int tid  = threadIdx.x;
    const int lane = tid & 31;
    const int wy   = tid >> 5;
    const int r    = blockIdx.x * 8 + wy;
    float4 sum = make_float4(0.f, 0.f, 0.f, 0.f);

    if (r < NNODES) {
        const int start = g_offs[r];
        const int deg   = g_rdeg[r];
        float4 acc = make_float4(0.f, 0.f, 0.f, 0.f);
        int j = 0;
        for (; j + 1 < deg; j += 2) {
            int s0 = g_csr[start + j];
            int s1 = g_csr[start + j + 1];
            float w0 = g_rss[s0];
            float w1 = g_rss[s1];
            uint2 a0 = *(const uint2*)&g_conv_h[(long)s0 * DD + lane * 4];
            uint2 a1 = *(const uint2*)&g_conv_h[(long)s1 * DD + lane * 4];
            float2 p00 = __half22float2(*(__half2*)&a0.x);
            float2 p01 = __half22float2(*(__half2*)&a0.y);
            float2 p10 = __half22float2(*(__half2*)&a1.x);
            float2 p11 = __half22float2(*(__half2*)&a1.y);
            acc.x = fmaf(p00.x, w0, fmaf(p10.x, w1, acc.x));
            acc.y = fmaf(p00.y, w0, fmaf(p10.y, w1, acc.y));
            acc.z = fmaf(p01.x, w0, fmaf(p11.x, w1, acc.z));
            acc.w = fmaf(p01.y, w0, fmaf(p11.y, w1, acc.w));
        }
        if (j < deg) {
            int s0 = g_csr[start + j];
            float w0 = g_rss[s0];
            uint2 a0 = *(const uint2*)&g_conv_h[(long)s0 * DD + lane * 4];
            float2 p00 = __half22float2(*(__half2*)&a0.x);
            float2 p01 = __half22float2(*(__half2*)&a0.y);
            acc.x = fmaf(p00.x, w0, acc.x);
            acc.y = fmaf(p00.y, w0, acc.y);
            acc.z = fmaf(p01.x, w0, acc.z);
            acc.w = fmaf(p01.y, w0, acc.w);
        }
        float rs = rsqrtf(fmaxf((float)deg, 1.0f));
        float4 gv = ((const float4*)g_gvec)[lane];
        long off = (long)r * 32 + lane;
        float4 h  = ((float4*)out)[off];
        float4 nd = ((const float4*)nodes)[off];
        float4 o;
        o.x = fmaxf(h.x + acc.x * rs + gv.x, 0.f) + nd.x;
        o.y = fmaxf(h.y + acc.y * rs + gv.y, 0.f) + nd.y;
        o.z = fmaxf(h.z + acc.z * rs + gv.z, 0.f) + nd.z;
        o.w = fmaxf(h.w + acc.w * rs + gv.w, 0.f) + nd.w;
        ((float4*)out)[off] = o;
        sum = o;
    }
    sred[tid] = sum;
    __syncthreads();
    if (wy == 0) {
        float4 s = sred[lane];
        #pragma unroll
        for (int jj = 1; jj < 8; jj++) {
            float4 t = sred[jj * 32 + lane];
            s.x += t.x; s.y += t.y; s.z += t.z; s.w += t.w;
        }
        float* addr = &g_an[lane * 4];
        asm volatile("red.global.add.v4.f32 [%0], {%1,%2,%3,%4};"
                     :: "l"(addr), "f"(s.x), "f"(s.y), "f"(s.z), "f"(s.w)
                     : "memory");
    }
}

// ---------------------------------------------------------------- global update
__global__ void k_global(const float* __restrict__ gl, const float* __restrict__ Wg,
                         const float* __restrict__ bg, float* __restrict__ outg) {
    __shared__ float red[2 * DD];
    int c = blockIdx.x, t = threadIdx.x;
    float x = (t < DD) ? g_an[t] : gl[t - DD];
    red[t] = x * Wg[t * DD + c];
    __syncthreads();
    if (t < 128) red[t] += red[t + 128];
    __syncthreads();
    if (t < 64) red[t] += red[t + 64];
    __syncthreads();
    if (t < 32) {
        float v = red[t] + red[t + 32];
        #pragma unroll
        for (int o = 16; o > 0; o >>= 1) v += __shfl_down_sync(0xffffffff, v, o);
        if (t == 0) outg[c] = gl[c] + fmaxf(v + bg[c], 0.f);
    }
}

// ---------------------------------------------------------------- launch (forked graph)
// Round-8 dataflow; k_gemm submitted 4th so the profiler captures it.
extern "C" void kernel_launch(void* const* d_in, const int* in_sizes, int n_in,
                              void* d_out, int out_size) {
    const float* nodes    = (const float*)d_in[0];
    const float* globals_ = (const float*)d_in[1];
    const int*   senders   = (const int*)d_in[2];
    const int*   receivers = (const int*)d_in[3];
    const float* W1w = (const float*)d_in[4];
    const float* W1b = (const float*)d_in[5];
    const float* W2w = (const float*)d_in[6];
    const float* W2b = (const float*)d_in[7];
    const float* W3w = (const float*)d_in[8];
    const float* W3b = (const float*)d_in[9];
    const float* Wgw = (const float*)d_in[10];
    const float* Wgb = (const float*)d_in[11];
    float* out = (float*)d_out;

    static cudaStream_t s1 = nullptr;
    static cudaEvent_t evRoot = nullptr, evSide = nullptr;
    if (s1 == nullptr) {
        cudaFuncSetAttribute(k_gemm, cudaFuncAttributeMaxDynamicSharedMemorySize, 64 * DD * 8);
        cudaStreamCreateWithFlags(&s1, cudaStreamNonBlocking);
        cudaEventCreateWithFlags(&evRoot, cudaEventDisableTiming);
        cudaEventCreateWithFlags(&evSide, cudaEventDisableTiming);
    }

    // fork
    cudaEventRecord(evRoot, 0);
    cudaStreamWaitEvent(s1, evRoot, 0);

    // side chain part 1 (s1): submissions #1-#3
    k_zero<<<(NNODES + 255) / 256, 256, 0, s1>>>(globals_, W3w, W3b);
    k_deg<<<(NEDGES + 255) / 256, 256, 0, s1>>>(senders, receivers);
    k_scanA<<<SCAN_BLK, 1024, 0, s1>>>();

    // main: dual GEMM — submission #4 (profiler target); independent of side chain
    dim3 gg((NNODES + 63) / 64, 2);
    k_gemm<<<gg, 256, 64 * DD * 8>>>(nodes, W1w, W1b, W2w, W2b, out);

    // side chain part 2 (s1): submissions #5-#7 (stream order on s1 preserved)
    k_scanB<<<1, 128, 0, s1>>>();
    k_scanC<<<(NNODES + 255) / 256, 256, 0, s1>>>();
    k_scatter<<<(NEDGES + 255) / 256, 256, 0, s1>>>(senders, receivers);
    cudaEventRecord(evSide, s1);

    // join -> pull-aggregate + fused epilogue -> global update
    cudaStreamWaitEvent(0, evSide, 0);
    k_gather<<<(NNODES + 7) / 8, 256>>>(nodes, out);
    k_global<<<DD, 2 * DD>>>(globals_, Wgw, Wgb, out + (long)NNODES * DD);
}

// round 11
// speedup vs baseline: 1.3153x; 1.0606x over previous
#include <cuda_runtime.h>
#include <cuda_fp16.h>
#include <math.h>
#include <stdint.h>

#define NNODES 100000
#define NEDGES 640000
#define DD 128
#define SCAN_BLK 98            // ceil(100000/1024)
#define RSTRIDE 129            // u64 per A-tile row (pad: rg groups 8 rows=8KB apart alias banks)
#define GEMM_SMEM (64 * RSTRIDE * 8)   // 66,048 B

// Scratch (__device__ globals: allocation-free rule)
__device__ __half g_conv_h[NNODES * DD];   // conv = nodes@W2 + b2 (UNSCALED), fp16
__device__ int    g_sdeg[NNODES];
__device__ int    g_rdeg[NNODES];
__device__ int    g_scan[NNODES];
__device__ int    g_bsum[SCAN_BLK];
__device__ int    g_boff[SCAN_BLK];
__device__ int    g_offs[NNODES];
__device__ int    g_cur[NNODES];
__device__ int    g_csr[NEDGES];
__device__ float  g_rss[NNODES];
__device__ float  g_gvec[DD];
__device__ float  g_an[DD];

// packed fp32x2 FMA
#define FMA_F32X2(acc, a, b) \
    asm("fma.rn.f32x2 %0, %1, %2, %0;" : "+l"(acc) : "l"(a), "l"(b))

__device__ __forceinline__ unsigned long long dup2(float f) {
    unsigned u = __float_as_uint(f);
    return (unsigned long long)u | ((unsigned long long)u << 32);
}
__device__ __forceinline__ float2 unpk(unsigned long long v) {
    return make_float2(__uint_as_float((unsigned)v), __uint_as_float((unsigned)(v >> 32)));
}

// ---------------------------------------------------------------- zero + gvec fused
__global__ void k_zero(const float* __restrict__ gl, const float* __restrict__ W3,
                       const float* __restrict__ b3) {
    int i = blockIdx.x * blockDim.x + threadIdx.x;
    if (i < NNODES) { g_sdeg[i] = 0; g_rdeg[i] = 0; }
    if (i < DD) g_an[i] = 0.f;
    if (blockIdx.x < DD) {
        __shared__ float red[DD];
        int c = blockIdx.x, t = threadIdx.x;
        if (t < DD) red[t] = gl[t] * W3[t * DD + c];
        __syncthreads();
        if (t < 64) red[t] += red[t + 64];
        __syncthreads();
        if (t < 32) {
            float v = red[t] + red[t + 32];
            #pragma unroll
            for (int o = 16; o > 0; o >>= 1) v += __shfl_down_sync(0xffffffff, v, o);
            if (t == 0) g_gvec[c] = v + b3[c];
        }
    }
}

// ---------------------------------------------------------------- degrees
__global__ void k_deg(const int* __restrict__ snd, const int* __restrict__ rcv) {
    int e = blockIdx.x * blockDim.x + threadIdx.x;
    if (e < NEDGES) {
        atomicAdd(&g_sdeg[snd[e]], 1);
        atomicAdd(&g_rdeg[rcv[e]], 1);
    }
}

// ---------------------------------------------------------------- prefix scan
__global__ __launch_bounds__(1024) void k_scanA() {
    __shared__ int sh[1024];
    int i = blockIdx.x * 1024 + threadIdx.x;
    int v = (i < NNODES) ? g_rdeg[i] : 0;
    sh[threadIdx.x] = v;
    __syncthreads();
    #pragma unroll
    for (int o = 1; o < 1024; o <<= 1) {
        int t = (threadIdx.x >= o) ? sh[threadIdx.x - o] : 0;
        __syncthreads();
        sh[threadIdx.x] += t;
        __syncthreads();
    }
    if (i < NNODES) g_scan[i] = sh[threadIdx.x];
    if (threadIdx.x == 1023) g_bsum[blockIdx.x] = sh[1023];
}
__global__ void k_scanB() {
    __shared__ int sh[128];
    int t = threadIdx.x;
    int v = (t < SCAN_BLK) ? g_bsum[t] : 0;
    sh[t] = v;
    __syncthreads();
    #pragma unroll
    for (int o = 1; o < 128; o <<= 1) {
        int u = (t >= o) ? sh[t - o] : 0;
        __syncthreads();
        sh[t] += u;
        __syncthreads();
    }
    if (t < SCAN_BLK) g_boff[t] = sh[t] - v;
}
__global__ void k_scanC() {
    int i = blockIdx.x * blockDim.x + threadIdx.x;
    if (i < NNODES) {
        int off = g_scan[i] - g_rdeg[i] + g_boff[i >> 10];
        g_offs[i] = off;
        g_cur[i]  = off;
        g_rss[i]  = rsqrtf(fmaxf((float)g_sdeg[i], 1.0f));
    }
}

// ---------------------------------------------------------------- CSR scatter
__global__ void k_scatter(const int* __restrict__ snd, const int* __restrict__ rcv) {
    int e = blockIdx.x * blockDim.x + threadIdx.x;
    if (e < NEDGES) {
        int r = rcv[e];
        int pos = atomicAdd(&g_cur[r], 1);
        g_csr[pos] = snd[e];
    }
}

// ---------------------------------------------------------------- f32x2 GEMM v2 (8x8 register tile)
// 128 thr/block, 64-row tile. Warp = 16 rows x 128 cols; thread = 8 rows x 8 cols.
// Per k per thread: 8 LDS.64 + 2 LDG.128 + 32 FFMA2  (FMA:LDS = 4:1).
extern __shared__ unsigned long long As2[];   // [64][RSTRIDE] u64
__global__ __launch_bounds__(128) void k_gemm(
    const float* __restrict__ A,
    const float* __restrict__ W1, const float* __restrict__ b1,
    const float* __restrict__ W2, const float* __restrict__ b2,
    float* __restrict__ out_h)
{
    const int which = blockIdx.y;
    const float* W    = which ? W2 : W1;
    const float* bias = which ? b2 : b1;
    const int rowBase = blockIdx.x * 64;
    const int tid = threadIdx.x;
    const int maxr = NNODES - rowBase;

    // Load + duplicate A tile [64 x 128] (2048 float4, 16 iters)
    const float4* A4 = (const float4*)(A + (long)rowBase * DD);
    #pragma unroll
    for (int i = 0; i < 16; i++) {
        int idx4 = tid + i * 128;
        int row = idx4 >> 5, col4 = (idx4 & 31) << 2;
        float4 v = make_float4(0.f, 0.f, 0.f, 0.f);
        if (row < maxr) v = A4[idx4];
        unsigned long long* d = &As2[row * RSTRIDE + col4];
        d[0] = dup2(v.x); d[1] = dup2(v.y); d[2] = dup2(v.z); d[3] = dup2(v.w);
    }
    __syncthreads();

    const int lane = tid & 31;
    const int wz   = tid >> 5;        // warp 0..3
    const int rg   = lane >> 4;       // row group 0/1
    const int c    = lane & 15;       // col group: cols c*8 .. c*8+7
    const int rowB = wz * 16 + rg * 8;

    unsigned long long acc[8][4];
    #pragma unroll
    for (int i = 0; i < 8; i++)
        { acc[i][0] = 0ull; acc[i][1] = 0ull; acc[i][2] = 0ull; acc[i][3] = 0ull; }

    const unsigned long long* Asrow = &As2[rowB * RSTRIDE];
    const float* Wc = W + c * 8;
    #pragma unroll 8
    for (int k = 0; k < DD; k++) {
        ulonglong2 wp0 = *(const ulonglong2*)(Wc + (long)k * DD);      // cols c*8..+3
        ulonglong2 wp1 = *(const ulonglong2*)(Wc + (long)k * DD + 4);  // cols c*8+4..+7
        #pragma unroll
        for (int i = 0; i < 8; i++) {
            unsigned long long ap = Asrow[i * RSTRIDE + k];            // 2-addr broadcast LDS.64
            FMA_F32X2(acc[i][0], ap, wp0.x);
            FMA_F32X2(acc[i][1], ap, wp0.y);
            FMA_F32X2(acc[i][2], ap, wp1.x);
            FMA_F32X2(acc[i][3], ap, wp1.y);
        }
    }

    float4 bv0 = *(const float4*)(bias + c * 8);
    float4 bv1 = *(const float4*)(bias + c * 8 + 4);
    #pragma unroll
    for (int i = 0; i < 8; i++) {
        int r = rowB + i;
        if (r < maxr) {
            int gr = rowBase + r;
            float2 p0 = unpk(acc[i][0]);
            float2 p1 = unpk(acc[i][1]);
            float2 p2 = unpk(acc[i][2]);
            float2 p3 = unpk(acc[i][3]);
            float4 oa = make_float4(p0.x + bv0.x, p0.y + bv0.y, p1.x + bv0.z, p1.y + bv0.w);
            float4 ob = make_float4(p2.x + bv1.x, p2.y + bv1.y, p3.x + bv1.z, p3.y + bv1.w);
            if (which) {
                __half2 h0 = __floats2half2_rn(oa.x, oa.y);
                __half2 h1 = __floats2half2_rn(oa.z, oa.w);
                __half2 h2 = __floats2half2_rn(ob.x, ob.y);
                __half2 h3 = __floats2half2_rn(ob.z, ob.w);
                uint4 pk;
                pk.x = *(unsigned*)&h0; pk.y = *(unsigned*)&h1;
                pk.z = *(unsigned*)&h2; pk.w = *(unsigned*)&h3;
                *(uint4*)&g_conv_h[(long)gr * DD + c * 8] = pk;
            } else {
                *(float4*)(out_h + (long)gr * DD + c * 8)     = oa;
                *(float4*)(out_h + (long)gr * DD + c * 8 + 4) = ob;
            }
        }
    }
}

// ---------------------------------------------------------------- CSR pull + fused epilogue
__global__ __launch_bounds__(256) void k_gather(const float* __restrict__ nodes,
                                                float* __restrict__ out) {
    __shared__ float4 sred[256];
    const int tid  = threadIdx.x;
    const int lane = tid & 31;
    const int wy   = tid >> 5;
    const int r    = blockIdx.x * 8 + wy;
    float4 sum = make_float4(0.f, 0.f, 0.f, 0.f);

    if (r < NNODES) {
        const int start = g_offs[r];
        const int deg   = g_rdeg[r];
        float4 acc = make_float4(0.f, 0.f, 0.f, 0.f);
        int j = 0;
        for (; j + 1 < deg; j += 2) {
            int s0 = g_csr[start + j];
            int s1 = g_csr[start + j + 1];
            float w0 = g_rss[s0];
            float w1 = g_rss[s1];
            uint2 a0 = *(const uint2*)&g_conv_h[(long)s0 * DD + lane * 4];
            uint2 a1 = *(const uint2*)&g_conv_h[(long)s1 * DD + lane * 4];
            float2 p00 = __half22float2(*(__half2*)&a0.x);
            float2 p01 = __half22float2(*(__half2*)&a0.y);
            float2 p10 = __half22float2(*(__half2*)&a1.x);
            float2 p11 = __half22float2(*(__half2*)&a1.y);
            acc.x = fmaf(p00.x, w0, fmaf(p10.x, w1, acc.x));
            acc.y = fmaf(p00.y, w0, fmaf(p10.y, w1, acc.y));
            acc.z = fmaf(p01.x, w0, fmaf(p11.x, w1, acc.z));
            acc.w = fmaf(p01.y, w0, fmaf(p11.y, w1, acc.w));
        }
        if (j < deg) {
            int s0 = g_csr[start + j];
            float w0 = g_rss[s0];
            uint2 a0 = *(const uint2*)&g_conv_h[(long)s0 * DD + lane * 4];
            float2 p00 = __half22float2(*(__half2*)&a0.x);
            float2 p01 = __half22float2(*(__half2*)&a0.y);
            acc.x = fmaf(p00.x, w0, acc.x);
            acc.y = fmaf(p00.y, w0, acc.y);
            acc.z = fmaf(p01.x, w0, acc.z);
            acc.w = fmaf(p01.y, w0, acc.w);
        }
        float rs = rsqrtf(fmaxf((float)deg, 1.0f));
        float4 gv = ((const float4*)g_gvec)[lane];
        long off = (long)r * 32 + lane;
        float4 h  = ((float4*)out)[off];
        float4 nd = ((const float4*)nodes)[off];
        float4 o;
        o.x = fmaxf(h.x + acc.x * rs + gv.x, 0.f) + nd.x;
        o.y = fmaxf(h.y + acc.y * rs + gv.y, 0.f) + nd.y;
        o.z = fmaxf(h.z + acc.z * rs + gv.z, 0.f) + nd.z;
        o.w = fmaxf(h.w + acc.w * rs + gv.w, 0.f) + nd.w;
        ((float4*)out)[off] = o;
        sum = o;
    }
    sred[tid] = sum;
    __syncthreads();
    if (wy == 0) {
        float4 s = sred[lane];
        #pragma unroll
        for (int jj = 1; jj < 8; jj++) {
            float4 t = sred[jj * 32 + lane];
            s.x += t.x; s.y += t.y; s.z += t.z; s.w += t.w;
        }
        float* addr = &g_an[lane * 4];
        asm volatile("red.global.add.v4.f32 [%0], {%1,%2,%3,%4};"
                     :: "l"(addr), "f"(s.x), "f"(s.y), "f"(s.z), "f"(s.w)
                     : "memory");
    }
}

// ---------------------------------------------------------------- global update
__global__ void k_global(const float* __restrict__ gl, const float* __restrict__ Wg,
                         const float* __restrict__ bg, float* __restrict__ outg) {
    __shared__ float red[2 * DD];
    int c = blockIdx.x, t = threadIdx.x;
    float x = (t < DD) ? g_an[t] : gl[t - DD];
    red[t] = x * Wg[t * DD + c];
    __syncthreads();
    if (t < 128) red[t] += red[t + 128];
    __syncthreads();
    if (t < 64) red[t] += red[t + 64];
    __syncthreads();
    if (t < 32) {
        float v = red[t] + red[t + 32];
        #pragma unroll
        for (int o = 16; o > 0; o >>= 1) v += __shfl_down_sync(0xffffffff, v, o);
        if (t == 0) outg[c] = gl[c] + fmaxf(v + bg[c], 0.f);
    }
}

// ---------------------------------------------------------------- launch (forked graph)
extern "C" void kernel_launch(void* const* d_in, const int* in_sizes, int n_in,
                              void* d_out, int out_size) {
    const float* nodes    = (const float*)d_in[0];
    const float* globals_ = (const float*)d_in[1];
    const int*   senders   = (const int*)d_in[2];
    const int*   receivers = (const int*)d_in[3];
    const float* W1w = (const float*)d_in[4];
    const float* W1b = (const float*)d_in[5];
    const float* W2w = (const float*)d_in[6];
    const float* W2b = (const float*)d_in[7];
    const float* W3w = (const float*)d_in[8];
    const float* W3b = (const float*)d_in[9];
    const float* Wgw = (const float*)d_in[10];
    const float* Wgb = (const float*)d_in[11];
    float* out = (float*)d_out;

    static cudaStream_t s1 = nullptr;
    static cudaEvent_t evRoot = nullptr, evSide = nullptr;
    if (s1 == nullptr) {
        cudaFuncSetAttribute(k_gemm, cudaFuncAttributeMaxDynamicSharedMemorySize, GEMM_SMEM);
        cudaStreamCreateWithFlags(&s1, cudaStreamNonBlocking);
        cudaEventCreateWithFlags(&evRoot, cudaEventDisableTiming);
        cudaEventCreateWithFlags(&evSide, cudaEventDisableTiming);
    }

    // fork
    cudaEventRecord(evRoot, 0);
    cudaStreamWaitEvent(s1, evRoot, 0);

    // side chain part 1 (s1): submissions #1-#3
    k_zero<<<(NNODES + 255) / 256, 256, 0, s1>>>(globals_, W3w, W3b);
    k_deg<<<(NEDGES + 255) / 256, 256, 0, s1>>>(senders, receivers);
    k_scanA<<<SCAN_BLK, 1024, 0, s1>>>();

    // main: dual GEMM — submission #4 (profiler target)
    dim3 gg((NNODES + 63) / 64, 2);
    k_gemm<<<gg, 128, GEMM_SMEM>>>(nodes, W1w, W1b, W2w, W2b, out);

    // side chain part 2 (s1)
    k_scanB<<<1, 128, 0, s1>>>();
    k_scanC<<<(NNODES + 255) / 256, 256, 0, s1>>>();
    k_scatter<<<(NEDGES + 255) / 256, 256, 0, s1>>>(senders, receivers);
    cudaEventRecord(evSide, s1);

    // join -> pull-aggregate + fused epilogue -> global update
    cudaStreamWaitEvent(0, evSide, 0);
    k_gather<<<(NNODES + 7) / 8, 256>>>(nodes, out);
    k_global<<<DD, 2 * DD>>>(globals_, Wgw, Wgb, out + (long)NNODES * DD);
}